// round 1
// baseline (speedup 1.0000x reference)
#include <cuda_runtime.h>
#include <math.h>

// Problem constants
#define B  32
#define C  200
#define H  56
#define W  56
#define HW 3136            // 56*56
#define OH 224
#define OW 224
#define KS 33
#define PAD 16

// Scratch (device globals; no runtime allocation)
__device__ float g_delta[(size_t)HW * C * B];   // [hw][c][b]  ~80.3 MB
__device__ float g_dist[(size_t)B * HW];        // [b][hw]
__device__ float g_up[(size_t)B * OH * OW];     // upsampled
__device__ float g_tmp[(size_t)B * OH * OW];    // blurH result
__device__ float g_gw[KS];                      // gaussian weights

// ---------------------------------------------------------------------------
// Kernel 1: delta transpose prepass.
// emb[b][c][hw], mean[c][hw]  ->  g_delta[hw][c][b]
// grid: (HW/32, C/8), 256 threads. Coalesced reads and writes via smem tile.
// ---------------------------------------------------------------------------
__global__ void prep_delta_kernel(const float* __restrict__ emb,
                                  const float* __restrict__ mean)
{
    __shared__ float s[8][32][33];  // [c_loc][b][hw_loc] (+pad)
    const int hw0 = blockIdx.x * 32;
    const int c0  = blockIdx.y * 8;
    const int lane = threadIdx.x & 31;
    const int wrp  = threadIdx.x >> 5;   // 8 warps, one c each

    const int c = c0 + wrp;
    const float m = mean[(size_t)c * HW + hw0 + lane];
    #pragma unroll 4
    for (int b = 0; b < B; b++) {
        float e = emb[((size_t)b * C + c) * HW + hw0 + lane];
        s[wrp][b][lane] = e - m;
    }
    __syncthreads();

    const int b  = threadIdx.x & 31;
    const int cl = threadIdx.x >> 5;
    #pragma unroll 4
    for (int hwl = 0; hwl < 32; hwl++) {
        g_delta[(size_t)(hw0 + hwl) * (C * B) + (c0 + cl) * B + b] = s[cl][b][hwl];
    }
}

// ---------------------------------------------------------------------------
// Kernel 2: per-pixel mahalanobis.
// One CTA per pixel p. q[b] = d_b^T M d_b, M = invcov[p] (200x200).
// Threads: 256 = 32 ty (4 rows each) x 8 tx (4 b each). Two row passes
// (rows 0..127, 128..199), M streamed in [rows][40] smem chunks.
// ---------------------------------------------------------------------------
#define TJ 40
#define MS_PITCH 41

__global__ void __launch_bounds__(256)
mahal_kernel(const float* __restrict__ invcov)
{
    __shared__ float Ds[C * B];            // 6400 floats, [j][b]
    __shared__ float Ms[128 * MS_PITCH];   // 5248 floats, [i_loc][j_loc] padded

    const int p   = blockIdx.x;
    const int tid = threadIdx.x;
    const int tx  = tid & 7;
    const int ty  = tid >> 3;
    const int b0  = tx * 4;

    // Load delta tile for this pixel (fully coalesced).
    const float* dsrc = g_delta + (size_t)p * (C * B);
    #pragma unroll
    for (int i = tid; i < C * B; i += 256) Ds[i] = dsrc[i];

    const float* Mp = invcov + (size_t)p * (C * C);

    float q0 = 0.f, q1 = 0.f, q2 = 0.f, q3 = 0.f;

    #pragma unroll
    for (int pass = 0; pass < 2; pass++) {
        const int base = pass * 128;
        const int nr   = pass ? (C - 128) : 128;     // 128 then 72
        const bool active = (ty * 4 < nr);

        float s00=0,s01=0,s02=0,s03=0;
        float s10=0,s11=0,s12=0,s13=0;
        float s20=0,s21=0,s22=0,s23=0;
        float s30=0,s31=0,s32=0,s33=0;

        for (int ch = 0; ch < C / TJ; ch++) {
            __syncthreads();   // protect Ms from previous chunk readers
            const int j0 = ch * TJ;
            const int total = nr * TJ;
            for (int e = tid; e < total; e += 256) {
                int il = e / TJ;
                int jl = e - il * TJ;
                Ms[il * MS_PITCH + jl] = Mp[(size_t)(base + il) * C + j0 + jl];
            }
            __syncthreads();

            if (active) {
                const float* mrow = &Ms[(ty * 4) * MS_PITCH];
                const float* drow = &Ds[j0 * B + b0];
                #pragma unroll 4
                for (int jl = 0; jl < TJ; jl++) {
                    float4 d4 = *(const float4*)(drow + jl * B);
                    float m0 = mrow[jl];
                    float m1 = mrow[MS_PITCH + jl];
                    float m2 = mrow[2 * MS_PITCH + jl];
                    float m3 = mrow[3 * MS_PITCH + jl];
                    s00 += m0 * d4.x; s01 += m0 * d4.y; s02 += m0 * d4.z; s03 += m0 * d4.w;
                    s10 += m1 * d4.x; s11 += m1 * d4.y; s12 += m1 * d4.z; s13 += m1 * d4.w;
                    s20 += m2 * d4.x; s21 += m2 * d4.y; s22 += m2 * d4.z; s23 += m2 * d4.w;
                    s30 += m3 * d4.x; s31 += m3 * d4.y; s32 += m3 * d4.z; s33 += m3 * d4.w;
                }
            }
        }

        if (active) {
            const int i0 = base + ty * 4;
            float4 di0 = *(const float4*)&Ds[(i0 + 0) * B + b0];
            float4 di1 = *(const float4*)&Ds[(i0 + 1) * B + b0];
            float4 di2 = *(const float4*)&Ds[(i0 + 2) * B + b0];
            float4 di3 = *(const float4*)&Ds[(i0 + 3) * B + b0];
            q0 += di0.x * s00 + di1.x * s10 + di2.x * s20 + di3.x * s30;
            q1 += di0.y * s01 + di1.y * s11 + di2.y * s21 + di3.y * s31;
            q2 += di0.z * s02 + di1.z * s12 + di2.z * s22 + di3.z * s32;
            q3 += di0.w * s03 + di1.w * s13 + di2.w * s23 + di3.w * s33;
        }
    }

    // Reduce 32 ty partials per b. Reuse Ms.
    __syncthreads();
    float* red = Ms;   // 32*33 floats needed <= 5248
    red[ty * 33 + b0 + 0] = q0;
    red[ty * 33 + b0 + 1] = q1;
    red[ty * 33 + b0 + 2] = q2;
    red[ty * 33 + b0 + 3] = q3;
    __syncthreads();
    if (tid < B) {
        float acc = 0.f;
        #pragma unroll
        for (int t = 0; t < 32; t++) acc += red[t * 33 + tid];
        g_dist[(size_t)tid * HW + p] = sqrtf(fmaxf(acc, 0.f));
    }
}

// ---------------------------------------------------------------------------
// Kernel 3: gaussian weight init (sigma = 4, ks = 33, normalized)
// ---------------------------------------------------------------------------
__global__ void gauss_init_kernel()
{
    if (threadIdx.x == 0 && blockIdx.x == 0) {
        float w[KS];
        float s = 0.f;
        for (int i = 0; i < KS; i++) {
            float x = (float)(i - (KS - 1) / 2);
            w[i] = expf(-(x * x) / (2.f * 16.f));
            s += w[i];
        }
        for (int i = 0; i < KS; i++) g_gw[i] = w[i] / s;
    }
}

// ---------------------------------------------------------------------------
// Kernel 4: bilinear upsample 56x56 -> 224x224, half-pixel centers,
// edge behavior == jax's weight renormalization == clamp.
// ---------------------------------------------------------------------------
__global__ void upsample_kernel()
{
    int idx = blockIdx.x * 256 + threadIdx.x;
    const int total = B * OH * OW;
    if (idx >= total) return;
    int x = idx % OW;
    int y = (idx / OW) % OH;
    int b = idx / (OW * OH);

    float sy = y * 0.25f - 0.375f;
    float sx = x * 0.25f - 0.375f;
    float fy0 = floorf(sy), fx0 = floorf(sx);
    float ay = sy - fy0, ax = sx - fx0;
    int y0 = (int)fy0, x0 = (int)fx0;
    int y1 = min(y0 + 1, H - 1);
    int x1 = min(x0 + 1, W - 1);
    y0 = max(y0, 0);
    x0 = max(x0, 0);

    const float* src = g_dist + (size_t)b * HW;
    float v00 = src[y0 * W + x0];
    float v01 = src[y0 * W + x1];
    float v10 = src[y1 * W + x0];
    float v11 = src[y1 * W + x1];
    float top = v00 + ax * (v01 - v00);
    float bot = v10 + ax * (v11 - v10);
    g_up[idx] = top + ay * (bot - top);
}

// ---------------------------------------------------------------------------
// Kernels 5/6: separable gaussian blur with reflect padding.
// reflect(i) over [0, N): i<0 -> -i ; i>=N -> 2N-2-i   (pad=16 < N=224, safe)
// ---------------------------------------------------------------------------
__device__ __forceinline__ int reflect224(int i)
{
    if (i < 0) i = -i;
    if (i > OW - 1) i = 2 * (OW - 1) - i;
    return i;
}

__global__ void blur_h_kernel()
{
    __shared__ float sgw[KS];
    if (threadIdx.x < KS) sgw[threadIdx.x] = g_gw[threadIdx.x];
    __syncthreads();

    int idx = blockIdx.x * 256 + threadIdx.x;
    const int total = B * OH * OW;
    if (idx >= total) return;
    int x = idx % OW;
    int row_base = idx - x;   // [b][y] row start

    float acc = 0.f;
    #pragma unroll
    for (int t = 0; t < KS; t++) {
        int xs = reflect224(x + t - PAD);
        acc += sgw[t] * g_up[row_base + xs];
    }
    g_tmp[idx] = acc;
}

__global__ void blur_v_kernel(float* __restrict__ out)
{
    __shared__ float sgw[KS];
    if (threadIdx.x < KS) sgw[threadIdx.x] = g_gw[threadIdx.x];
    __syncthreads();

    int idx = blockIdx.x * 256 + threadIdx.x;
    const int total = B * OH * OW;
    if (idx >= total) return;
    int x = idx % OW;
    int y = (idx / OW) % OH;
    int b = idx / (OW * OH);
    const float* src = g_tmp + (size_t)b * OH * OW;

    float acc = 0.f;
    #pragma unroll
    for (int t = 0; t < KS; t++) {
        int ys = reflect224(y + t - PAD);
        acc += sgw[t] * src[ys * OW + x];
    }
    out[idx] = acc;
}

// ---------------------------------------------------------------------------
// Launch
// inputs: [0] embedding (B,C,H,W) f32, [1] mean (C,HW) f32,
//         [2] inv_covariance (HW,C,C) f32, [3] covariance (unused)
// output: (B,1,224,224) f32
// ---------------------------------------------------------------------------
extern "C" void kernel_launch(void* const* d_in, const int* in_sizes, int n_in,
                              void* d_out, int out_size)
{
    const float* emb    = (const float*)d_in[0];
    const float* mean   = (const float*)d_in[1];
    const float* invcov = (const float*)d_in[2];
    float* out = (float*)d_out;

    dim3 prep_grid(HW / 32, C / 8);
    prep_delta_kernel<<<prep_grid, 256>>>(emb, mean);

    mahal_kernel<<<HW, 256>>>(invcov);

    gauss_init_kernel<<<1, 32>>>();

    const int total = B * OH * OW;
    const int nb = (total + 255) / 256;
    upsample_kernel<<<nb, 256>>>();
    blur_h_kernel<<<nb, 256>>>();
    blur_v_kernel<<<nb, 256>>>(out);
}

// round 2
// speedup vs baseline: 1.6589x; 1.6589x over previous
#include <cuda_runtime.h>
#include <math.h>

// Problem constants
#define B  32
#define C  200
#define H  56
#define W  56
#define HW 3136
#define OH 224
#define OW 224
#define KS 33
#define PAD 16

#define MSP 44          // M chunk smem pitch (floats): 176B rows, 16B aligned, conflict-free

// Scratch (device globals)
__device__ float g_delta[(size_t)HW * C * B];   // [hw][c][b]
__device__ float g_dist[(size_t)B * HW];
__device__ float g_up[(size_t)B * OH * OW];
__device__ float g_tmp[(size_t)B * OH * OW];
__device__ float g_gw[KS];

// ---------------- packed f32x2 helpers ----------------
__device__ __forceinline__ unsigned long long fma2(unsigned long long a,
                                                   unsigned long long b,
                                                   unsigned long long c)
{
    unsigned long long d;
    asm("fma.rn.f32x2 %0, %1, %2, %3;" : "=l"(d) : "l"(a), "l"(b), "l"(c));
    return d;
}
__device__ __forceinline__ unsigned long long pack2(float x)
{
    unsigned long long d;
    asm("mov.b64 %0, {%1, %1};" : "=l"(d) : "f"(x));
    return d;
}
__device__ __forceinline__ float2 unpack2(unsigned long long v)
{
    float2 r;
    asm("mov.b64 {%0, %1}, %2;" : "=f"(r.x), "=f"(r.y) : "l"(v));
    return r;
}

// ---------------------------------------------------------------------------
// Kernel 1: delta transpose prepass: emb[b][c][hw] -> g_delta[hw][c][b]
// ---------------------------------------------------------------------------
__global__ void prep_delta_kernel(const float* __restrict__ emb,
                                  const float* __restrict__ mean)
{
    __shared__ float s[8][32][33];
    const int hw0 = blockIdx.x * 32;
    const int c0  = blockIdx.y * 8;
    const int lane = threadIdx.x & 31;
    const int wrp  = threadIdx.x >> 5;

    const int c = c0 + wrp;
    const float m = mean[(size_t)c * HW + hw0 + lane];
    #pragma unroll 4
    for (int b = 0; b < B; b++) {
        float e = emb[((size_t)b * C + c) * HW + hw0 + lane];
        s[wrp][b][lane] = e - m;
    }
    __syncthreads();

    const int b  = threadIdx.x & 31;
    const int cl = threadIdx.x >> 5;
    #pragma unroll 4
    for (int hwl = 0; hwl < 32; hwl++) {
        g_delta[(size_t)(hw0 + hwl) * (C * B) + (c0 + cl) * B + b] = s[cl][b][hwl];
    }
}

// ---------------------------------------------------------------------------
// Kernel 2: per-pixel mahalanobis, f32x2-packed, double-buffered.
// CTA = 1 pixel. 256 thr = 8 tx (4 b each, packed as 2 f32x2) x 32 ty.
// Rows in 2 passes (128 + 72), rows per thread strided by 32.
// M streamed in [rows x 40] chunks, register-staged double buffer.
// ---------------------------------------------------------------------------
__global__ void __launch_bounds__(256)
mahal_kernel(const float* __restrict__ invcov)
{
    extern __shared__ float sm[];
    float* Ds = sm;                            // 6400 floats [j][b]
    float* Mb0 = sm + C * B;                   // 128*44
    float* Mb1 = Mb0 + 128 * MSP;              // 128*44

    const int p   = blockIdx.x;
    const int tid = threadIdx.x;
    const int tx  = tid & 7;
    const int ty  = tid >> 3;
    const int b0  = tx * 4;

    // Load delta tile (coalesced float4)
    const float* dsrc = g_delta + (size_t)p * (C * B);
    #pragma unroll
    for (int i = tid * 4; i < C * B; i += 1024)
        *(float4*)&Ds[i] = *(const float4*)&dsrc[i];

    const float* Mp = invcov + (size_t)p * (C * C);

    float q0 = 0.f, q1 = 0.f, q2 = 0.f, q3 = 0.f;

    // ======================= pass 1: rows 0..127 =======================
    {
        unsigned long long acc[4][2] = {{0ull,0ull},{0ull,0ull},{0ull,0ull},{0ull,0ull}};
        float4 st[5];

        // prefetch chunk 0: warp-interleaved float4 (contiguous 512B per LDG.128 warp-op)
        #pragma unroll
        for (int o = 0; o < 5; o++) {
            int e = (o * 256 + tid) * 4;           // 1280 float4 = 128*40
            int il = e / 40, jl = e % 40;
            st[o] = *(const float4*)&Mp[(size_t)il * C + jl];
        }

        #pragma unroll
        for (int ch = 0; ch < 5; ch++) {
            float* buf = (ch & 1) ? Mb1 : Mb0;
            __syncthreads();                       // prior readers of buf done
            #pragma unroll
            for (int o = 0; o < 5; o++) {
                int e = (o * 256 + tid) * 4;
                int il = e / 40, jl = e % 40;
                *(float4*)&buf[il * MSP + jl] = st[o];
            }
            __syncthreads();

            if (ch < 4) {                          // prefetch next chunk
                int j0n = (ch + 1) * 40;
                #pragma unroll
                for (int o = 0; o < 5; o++) {
                    int e = (o * 256 + tid) * 4;
                    int il = e / 40, jl = e % 40;
                    st[o] = *(const float4*)&Mp[(size_t)il * C + j0n + jl];
                }
            }

            const int j0 = ch * 40;
            #pragma unroll
            for (int blk = 0; blk < 10; blk++) {
                float4 mv0 = *(const float4*)&buf[(ty      ) * MSP + blk * 4];
                float4 mv1 = *(const float4*)&buf[(ty +  32) * MSP + blk * 4];
                float4 mv2 = *(const float4*)&buf[(ty +  64) * MSP + blk * 4];
                float4 mv3 = *(const float4*)&buf[(ty +  96) * MSP + blk * 4];
                const float* dsb = &Ds[(j0 + blk * 4) * B + b0];
                #pragma unroll
                for (int jj = 0; jj < 4; jj++) {
                    ulonglong2 du = *(const ulonglong2*)(dsb + jj * B);
                    float c0 = (jj==0)?mv0.x:(jj==1)?mv0.y:(jj==2)?mv0.z:mv0.w;
                    float c1 = (jj==0)?mv1.x:(jj==1)?mv1.y:(jj==2)?mv1.z:mv1.w;
                    float c2 = (jj==0)?mv2.x:(jj==1)?mv2.y:(jj==2)?mv2.z:mv2.w;
                    float c3 = (jj==0)?mv3.x:(jj==1)?mv3.y:(jj==2)?mv3.z:mv3.w;
                    unsigned long long m0 = pack2(c0);
                    acc[0][0] = fma2(m0, du.x, acc[0][0]);
                    acc[0][1] = fma2(m0, du.y, acc[0][1]);
                    unsigned long long m1 = pack2(c1);
                    acc[1][0] = fma2(m1, du.x, acc[1][0]);
                    acc[1][1] = fma2(m1, du.y, acc[1][1]);
                    unsigned long long m2 = pack2(c2);
                    acc[2][0] = fma2(m2, du.x, acc[2][0]);
                    acc[2][1] = fma2(m2, du.y, acc[2][1]);
                    unsigned long long m3 = pack2(c3);
                    acc[3][0] = fma2(m3, du.x, acc[3][0]);
                    acc[3][1] = fma2(m3, du.y, acc[3][1]);
                }
            }
        }

        // fold: q_b += d_i * s_i
        #pragma unroll
        for (int k = 0; k < 4; k++) {
            int i = ty + 32 * k;
            float4 dv = *(const float4*)&Ds[i * B + b0];
            float2 s0 = unpack2(acc[k][0]);
            float2 s1 = unpack2(acc[k][1]);
            q0 += dv.x * s0.x; q1 += dv.y * s0.y;
            q2 += dv.z * s1.x; q3 += dv.w * s1.y;
        }
    }

    // ======================= pass 2: rows 128..199 (72) =======================
    {
        unsigned long long acc[3][2] = {{0ull,0ull},{0ull,0ull},{0ull,0ull}};
        const bool k2 = (ty < 8);
        const float* Mp2 = Mp + (size_t)128 * C;
        float4 st[3];

        #pragma unroll
        for (int o = 0; o < 3; o++) {
            int e4 = o * 256 + tid;                // 720 float4 = 72*40
            if (e4 < 720) {
                int e = e4 * 4;
                int il = e / 40, jl = e % 40;
                st[o] = *(const float4*)&Mp2[(size_t)il * C + jl];
            }
        }

        #pragma unroll
        for (int ch = 0; ch < 5; ch++) {
            float* buf = (ch & 1) ? Mb1 : Mb0;
            __syncthreads();
            #pragma unroll
            for (int o = 0; o < 3; o++) {
                int e4 = o * 256 + tid;
                if (e4 < 720) {
                    int e = e4 * 4;
                    int il = e / 40, jl = e % 40;
                    *(float4*)&buf[il * MSP + jl] = st[o];
                }
            }
            __syncthreads();

            if (ch < 4) {
                int j0n = (ch + 1) * 40;
                #pragma unroll
                for (int o = 0; o < 3; o++) {
                    int e4 = o * 256 + tid;
                    if (e4 < 720) {
                        int e = e4 * 4;
                        int il = e / 40, jl = e % 40;
                        st[o] = *(const float4*)&Mp2[(size_t)il * C + j0n + jl];
                    }
                }
            }

            const int j0 = ch * 40;
            #pragma unroll
            for (int blk = 0; blk < 10; blk++) {
                float4 mv0 = *(const float4*)&buf[(ty      ) * MSP + blk * 4];
                float4 mv1 = *(const float4*)&buf[(ty +  32) * MSP + blk * 4];
                float4 mv2 = make_float4(0.f, 0.f, 0.f, 0.f);
                if (k2) mv2 = *(const float4*)&buf[(ty + 64) * MSP + blk * 4];
                const float* dsb = &Ds[(j0 + blk * 4) * B + b0];
                #pragma unroll
                for (int jj = 0; jj < 4; jj++) {
                    ulonglong2 du = *(const ulonglong2*)(dsb + jj * B);
                    float c0 = (jj==0)?mv0.x:(jj==1)?mv0.y:(jj==2)?mv0.z:mv0.w;
                    float c1 = (jj==0)?mv1.x:(jj==1)?mv1.y:(jj==2)?mv1.z:mv1.w;
                    float c2 = (jj==0)?mv2.x:(jj==1)?mv2.y:(jj==2)?mv2.z:mv2.w;
                    unsigned long long m0 = pack2(c0);
                    acc[0][0] = fma2(m0, du.x, acc[0][0]);
                    acc[0][1] = fma2(m0, du.y, acc[0][1]);
                    unsigned long long m1 = pack2(c1);
                    acc[1][0] = fma2(m1, du.x, acc[1][0]);
                    acc[1][1] = fma2(m1, du.y, acc[1][1]);
                    unsigned long long m2 = pack2(c2);
                    acc[2][0] = fma2(m2, du.x, acc[2][0]);
                    acc[2][1] = fma2(m2, du.y, acc[2][1]);
                }
            }
        }

        #pragma unroll
        for (int k = 0; k < 2; k++) {
            int i = 128 + ty + 32 * k;
            float4 dv = *(const float4*)&Ds[i * B + b0];
            float2 s0 = unpack2(acc[k][0]);
            float2 s1 = unpack2(acc[k][1]);
            q0 += dv.x * s0.x; q1 += dv.y * s0.y;
            q2 += dv.z * s1.x; q3 += dv.w * s1.y;
        }
        if (k2) {
            int i = 192 + ty;
            float4 dv = *(const float4*)&Ds[i * B + b0];
            float2 s0 = unpack2(acc[2][0]);
            float2 s1 = unpack2(acc[2][1]);
            q0 += dv.x * s0.x; q1 += dv.y * s0.y;
            q2 += dv.z * s1.x; q3 += dv.w * s1.y;
        }
    }

    // block reduction over ty
    __syncthreads();
    float* red = Mb0;                  // 32*33 floats scratch
    red[ty * 33 + b0 + 0] = q0;
    red[ty * 33 + b0 + 1] = q1;
    red[ty * 33 + b0 + 2] = q2;
    red[ty * 33 + b0 + 3] = q3;
    __syncthreads();
    if (tid < B) {
        float acc = 0.f;
        #pragma unroll
        for (int t = 0; t < 32; t++) acc += red[t * 33 + tid];
        g_dist[(size_t)tid * HW + p] = sqrtf(fmaxf(acc, 0.f));
    }
}

// ---------------------------------------------------------------------------
// Kernel 3: gaussian weight init
// ---------------------------------------------------------------------------
__global__ void gauss_init_kernel()
{
    if (threadIdx.x == 0 && blockIdx.x == 0) {
        float w[KS];
        float s = 0.f;
        for (int i = 0; i < KS; i++) {
            float x = (float)(i - (KS - 1) / 2);
            w[i] = expf(-(x * x) / (2.f * 16.f));
            s += w[i];
        }
        for (int i = 0; i < KS; i++) g_gw[i] = w[i] / s;
    }
}

// ---------------------------------------------------------------------------
// Kernel 4: bilinear upsample 56x56 -> 224x224
// ---------------------------------------------------------------------------
__global__ void upsample_kernel()
{
    int idx = blockIdx.x * 256 + threadIdx.x;
    const int total = B * OH * OW;
    if (idx >= total) return;
    int x = idx % OW;
    int y = (idx / OW) % OH;
    int b = idx / (OW * OH);

    float sy = y * 0.25f - 0.375f;
    float sx = x * 0.25f - 0.375f;
    float fy0 = floorf(sy), fx0 = floorf(sx);
    float ay = sy - fy0, ax = sx - fx0;
    int y0 = (int)fy0, x0 = (int)fx0;
    int y1 = min(y0 + 1, H - 1);
    int x1 = min(x0 + 1, W - 1);
    y0 = max(y0, 0);
    x0 = max(x0, 0);

    const float* src = g_dist + (size_t)b * HW;
    float v00 = src[y0 * W + x0];
    float v01 = src[y0 * W + x1];
    float v10 = src[y1 * W + x0];
    float v11 = src[y1 * W + x1];
    float top = v00 + ax * (v01 - v00);
    float bot = v10 + ax * (v11 - v10);
    g_up[idx] = top + ay * (bot - top);
}

// ---------------------------------------------------------------------------
// Kernels 5/6: separable gaussian blur, reflect padding
// ---------------------------------------------------------------------------
__device__ __forceinline__ int reflect224(int i)
{
    if (i < 0) i = -i;
    if (i > OW - 1) i = 2 * (OW - 1) - i;
    return i;
}

__global__ void blur_h_kernel()
{
    __shared__ float sgw[KS];
    if (threadIdx.x < KS) sgw[threadIdx.x] = g_gw[threadIdx.x];
    __syncthreads();

    int idx = blockIdx.x * 256 + threadIdx.x;
    const int total = B * OH * OW;
    if (idx >= total) return;
    int x = idx % OW;
    int row_base = idx - x;

    float acc = 0.f;
    #pragma unroll
    for (int t = 0; t < KS; t++) {
        int xs = reflect224(x + t - PAD);
        acc += sgw[t] * g_up[row_base + xs];
    }
    g_tmp[idx] = acc;
}

__global__ void blur_v_kernel(float* __restrict__ out)
{
    __shared__ float sgw[KS];
    if (threadIdx.x < KS) sgw[threadIdx.x] = g_gw[threadIdx.x];
    __syncthreads();

    int idx = blockIdx.x * 256 + threadIdx.x;
    const int total = B * OH * OW;
    if (idx >= total) return;
    int x = idx % OW;
    int y = (idx / OW) % OH;
    int b = idx / (OW * OH);
    const float* src = g_tmp + (size_t)b * OH * OW;

    float acc = 0.f;
    #pragma unroll
    for (int t = 0; t < KS; t++) {
        int ys = reflect224(y + t - PAD);
        acc += sgw[t] * src[ys * OW + x];
    }
    out[idx] = acc;
}

// ---------------------------------------------------------------------------
// Launch
// ---------------------------------------------------------------------------
extern "C" void kernel_launch(void* const* d_in, const int* in_sizes, int n_in,
                              void* d_out, int out_size)
{
    const float* emb    = (const float*)d_in[0];
    const float* mean   = (const float*)d_in[1];
    const float* invcov = (const float*)d_in[2];
    float* out = (float*)d_out;

    const int mahal_smem = (C * B + 2 * 128 * MSP) * (int)sizeof(float);  // 70656
    cudaFuncSetAttribute(mahal_kernel,
                         cudaFuncAttributeMaxDynamicSharedMemorySize, mahal_smem);

    dim3 prep_grid(HW / 32, C / 8);
    prep_delta_kernel<<<prep_grid, 256>>>(emb, mean);

    mahal_kernel<<<HW, 256, mahal_smem>>>(invcov);

    gauss_init_kernel<<<1, 32>>>();

    const int total = B * OH * OW;
    const int nb = (total + 255) / 256;
    upsample_kernel<<<nb, 256>>>();
    blur_h_kernel<<<nb, 256>>>();
    blur_v_kernel<<<nb, 256>>>(out);
}